// round 9
// baseline (speedup 1.0000x reference)
#include <cuda_runtime.h>
#include <cstdint>

#define IN_H   1024
#define IN_W   1024
#define OUT_H  256
#define OUT_W  256
#define NTAP   16

#define VCHUNK 8                 // output rows per strip
#define G      4                 // input rows per TMA group (16 KB contiguous)
#define NG     11                // 44 input rows = 11 groups
#define STRIPS_PER_BLOCK 2
#define XBLKS  (OUT_H / VCHUNK / STRIPS_PER_BLOCK)   // 16
#define GROUP_BYTES (G * IN_W * 4)                   // 16384

__device__ __forceinline__ uint32_t s2u(const void* p) {
    return (uint32_t)__cvta_generic_to_shared(p);
}
__device__ __forceinline__ void mbar_init(uint32_t m, uint32_t cnt) {
    asm volatile("mbarrier.init.shared.b64 [%0], %1;" :: "r"(m), "r"(cnt) : "memory");
}
__device__ __forceinline__ void mbar_expect_tx(uint32_t m, uint32_t bytes) {
    asm volatile("mbarrier.arrive.expect_tx.shared.b64 _, [%0], %1;"
                 :: "r"(m), "r"(bytes) : "memory");
}
__device__ __forceinline__ void bulk_g2s(uint32_t dst, const void* src,
                                         uint32_t bytes, uint32_t m) {
    asm volatile("cp.async.bulk.shared::cta.global.mbarrier::complete_tx::bytes "
                 "[%0], [%1], %2, [%3];"
                 :: "r"(dst), "l"(src), "r"(bytes), "r"(m) : "memory");
}
__device__ __forceinline__ void mbar_wait(uint32_t m, uint32_t parity) {
    asm volatile("{\n\t.reg .pred P;\n"
                 "W_%=:\n\t"
                 "mbarrier.try_wait.parity.acquire.cta.shared::cta.b64 P, [%0], %1, 0x989680;\n\t"
                 "@!P bra W_%=;\n\t}"
                 :: "r"(m), "r"(parity) : "memory");
}

// horizontal 16-tap for one vertical-result row held in smem
__device__ __forceinline__ void hfilter(const float* __restrict__ srow,
                                        int oc, float* __restrict__ dst)
{
    constexpr float W[NTAP] = {
        -0.001708984375f, -0.010986328125f, -0.018310546875f, -0.011962890625f,
         0.022705078125f,  0.097412109375f,  0.181884765625f,  0.240966796875f,
         0.240966796875f,  0.181884765625f,  0.097412109375f,  0.022705078125f,
        -0.011962890625f, -0.018310546875f, -0.010986328125f, -0.001708984375f };
    float r;
    if (oc >= 2 && oc <= 253) {
        const float4* __restrict__ sv = (const float4*)srow + oc;
        const float4 a = sv[-2], b = sv[-1], c = sv[0], d = sv[1], e = sv[2];
        r = W[0] * a.z;
        r = fmaf(W[1],  a.w, r);  r = fmaf(W[2],  b.x, r);
        r = fmaf(W[3],  b.y, r);  r = fmaf(W[4],  b.z, r);
        r = fmaf(W[5],  b.w, r);  r = fmaf(W[6],  c.x, r);
        r = fmaf(W[7],  c.y, r);  r = fmaf(W[8],  c.z, r);
        r = fmaf(W[9],  c.w, r);  r = fmaf(W[10], d.x, r);
        r = fmaf(W[11], d.y, r);  r = fmaf(W[12], d.z, r);
        r = fmaf(W[13], d.w, r);  r = fmaf(W[14], e.x, r);
        r = fmaf(W[15], e.y, r);
    } else {
        r = 0.f;
#pragma unroll
        for (int k = 0; k < NTAP; ++k)
            r = fmaf(W[k], srow[min(max(4 * oc - 6 + k, 0), IN_W - 1)], r);
    }
    *dst = r;
}

__global__ __launch_bounds__(256)
void bicubic_fused(const float* __restrict__ in, float* __restrict__ out)
{
    constexpr float W[NTAP] = {
        -0.001708984375f, -0.010986328125f, -0.018310546875f, -0.011962890625f,
         0.022705078125f,  0.097412109375f,  0.181884765625f,  0.240966796875f,
         0.240966796875f,  0.181884765625f,  0.097412109375f,  0.022705078125f,
        -0.011962890625f, -0.018310546875f, -0.010986328125f, -0.001708984375f };

    __shared__ __align__(16) float in_buf[3][G][IN_W];   // 48 KB TMA ring
    __shared__ __align__(16) float s_row[2][IN_W];       //  8 KB V-result rows
    __shared__ __align__(8)  unsigned long long mbar_s[3];

    const int tid = threadIdx.x;
    const int img = blockIdx.y;
    const float* __restrict__ inp = in + (size_t)img * (IN_H * IN_W);

    uint32_t mb[3];
#pragma unroll
    for (int s = 0; s < 3; ++s) mb[s] = s2u(&mbar_s[s]);

    if (tid == 0) {
#pragma unroll
        for (int s = 0; s < 3; ++s) mbar_init(mb[s], 1);
    }
    __syncthreads();

#pragma unroll 1
    for (int it = 0; it < STRIPS_PER_BLOCK; ++it) {
        const int strip = blockIdx.x + XBLKS * it;       // adjacent strips co-run
        const int o0    = strip * VCHUNK;
        const int R0    = 4 * o0 - 6;
        const int qbase = it * NG;                       // global group counter base
        float* __restrict__ outp = out + ((size_t)img * OUT_H + o0) * OUT_W;

        // single-thread TMA issue for group g (stage = q%3)
        auto issue = [&](int g) {
            if (tid == 0) {
                const int q = qbase + g;
                const uint32_t m   = mb[q % 3];
                const uint32_t dst = s2u(&in_buf[q % 3][0][0]);
                mbar_expect_tx(m, GROUP_BYTES);
                const int r0 = R0 + 4 * g;
                if (r0 >= 0 && r0 + G <= IN_H) {
                    bulk_g2s(dst, inp + (size_t)r0 * IN_W, GROUP_BYTES, m);
                } else {
#pragma unroll
                    for (int r = 0; r < G; ++r) {
                        const int gr = min(max(r0 + r, 0), IN_H - 1);
                        bulk_g2s(dst + r * IN_W * 4, inp + (size_t)gr * IN_W,
                                 IN_W * 4, m);
                    }
                }
            }
        };

        issue(0);
        issue(1);

        float4 acc[VCHUNK];
#pragma unroll
        for (int j = 0; j < VCHUNK; ++j) acc[j] = make_float4(0.f, 0.f, 0.f, 0.f);

#pragma unroll
        for (int g = 0; g < NG; ++g) {
            const int q = qbase + g;
            mbar_wait(mb[q % 3], (q / 3) & 1);
            __syncthreads();                   // orders s_row STS(g-1) -> LDS(g),
                                               // and prior reads of stage (q+2)%3
            if (g + 2 < NG) issue(g + 2);      // keep 2 groups in flight

            // H phase for output row (g-4), staged last iteration
            if (g >= 4)
                hfilter(s_row[g % 2], tid, outp + (size_t)(g - 4) * OUT_W + tid);

            // V phase: consume group g
            const float4* __restrict__ buf = (const float4*)in_buf[q % 3];
#pragma unroll
            for (int r = 0; r < G; ++r) {
                const int i = 4 * g + r;
                const float4 v = buf[r * (IN_W / 4) + tid];
#pragma unroll
                for (int j = 0; j < VCHUNK; ++j) {
                    const int k = i - 4 * j;           // compile-time pruned
                    if (k >= 0 && k < NTAP) {
                        acc[j].x = fmaf(W[k], v.x, acc[j].x);
                        acc[j].y = fmaf(W[k], v.y, acc[j].y);
                        acc[j].z = fmaf(W[k], v.z, acc[j].z);
                        acc[j].w = fmaf(W[k], v.w, acc[j].w);
                    }
                }
            }

            // output row g-3 complete -> stage for next iteration's H
            if (g >= 3)
                ((float4*)s_row[(g - 3) % 2])[tid] = acc[g - 3];
        }

        __syncthreads();
        hfilter(s_row[1], tid, outp + (size_t)7 * OUT_W + tid);   // last row (j=7)
        __syncthreads();                       // s_row/in_buf safe before next strip
    }
}

extern "C" void kernel_launch(void* const* d_in, const int* in_sizes, int n_in,
                              void* d_out, int out_size)
{
    const float* in  = (const float*)d_in[0];
    float*       out = (float*)d_out;

    const int nimg = in_sizes[0] / (IN_H * IN_W);       // 24

    dim3 grid(XBLKS, nimg);                             // 16 x 24 = 384 blocks
    bicubic_fused<<<grid, 256>>>(in, out);
}

// round 10
// speedup vs baseline: 1.1371x; 1.1371x over previous
#include <cuda_runtime.h>
#include <cstdint>

#define IN_H   1024
#define IN_W   1024
#define OUT_H  256
#define OUT_W  256
#define NTAP   16

#define VCHUNK 8                 // output rows per strip
#define G      4                 // input rows per cp.async group
#define NG     11                // 44 input rows = 11 groups
#define STRIPS_PER_BLOCK 2
#define XBLKS  (OUT_H / VCHUNK / STRIPS_PER_BLOCK)   // 16

__device__ __forceinline__ void cp_async16(uint32_t dst_smem, const float* src) {
    asm volatile("cp.async.cg.shared.global [%0], [%1], 16;\n"
                 :: "r"(dst_smem), "l"(src) : "memory");
}
__device__ __forceinline__ void cp_commit() {
    asm volatile("cp.async.commit_group;\n" ::: "memory");
}
template <int N>
__device__ __forceinline__ void cp_wait() {
    asm volatile("cp.async.wait_group %0;\n" :: "n"(N) : "memory");
}

__global__ __launch_bounds__(256)
void bicubic_fused(const float* __restrict__ in, float* __restrict__ out)
{
    constexpr float W[NTAP] = {
        -0.001708984375f, -0.010986328125f, -0.018310546875f, -0.011962890625f,
         0.022705078125f,  0.097412109375f,  0.181884765625f,  0.240966796875f,
         0.240966796875f,  0.181884765625f,  0.097412109375f,  0.022705078125f,
        -0.011962890625f, -0.018310546875f, -0.010986328125f, -0.001708984375f };

    // 48 KB ring; after the V loop it is reinterpreted as v[8][1024] (32 KB)
    __shared__ __align__(16) float ring[3][G][IN_W];
    float (*v)[IN_W] = (float (*)[IN_W])&ring[0][0][0];

    const int tid = threadIdx.x;                 // owns float4 column tid
    const int img = blockIdx.y;
    const float* __restrict__ inp = in + (size_t)img * (IN_H * IN_W);

#pragma unroll 1
    for (int it = 0; it < STRIPS_PER_BLOCK; ++it) {
        const int strip = blockIdx.x + XBLKS * it;       // adjacent strips co-run
        const int o0    = strip * VCHUNK;
        const int R0    = 4 * o0 - 6;
        float* __restrict__ outp = out + ((size_t)img * OUT_H + o0) * OUT_W;

        // per-thread prefetch of group g into ring[g%3] (own 16 B per row)
        auto prefetch = [&](int g) {
#pragma unroll
            for (int r = 0; r < G; ++r) {
                const int gr = min(max(R0 + 4 * g + r, 0), IN_H - 1);
                const uint32_t dst = (uint32_t)__cvta_generic_to_shared(
                    &ring[g % 3][r][4 * tid]);
                cp_async16(dst, inp + (size_t)gr * IN_W + 4 * tid);
            }
            cp_commit();
        };

        prefetch(0);
        prefetch(1);

        float4 acc[VCHUNK];
#pragma unroll
        for (int j = 0; j < VCHUNK; ++j) acc[j] = make_float4(0.f, 0.f, 0.f, 0.f);

        // ---- barrier-free V mainloop: thread-private producer/consumer ----
#pragma unroll
        for (int g = 0; g < NG; ++g) {
            if (g < NG - 1) cp_wait<1>(); else cp_wait<0>();

            if (g + 2 < NG) prefetch(g + 2);   // keep 2 groups in flight

            const float4* __restrict__ buf = (const float4*)ring[g % 3];
#pragma unroll
            for (int r = 0; r < G; ++r) {
                const int i = 4 * g + r;
                const float4 x = buf[r * (IN_W / 4) + tid];
#pragma unroll
                for (int j = 0; j < VCHUNK; ++j) {
                    const int k = i - 4 * j;           // compile-time pruned
                    if (k >= 0 && k < NTAP) {
                        acc[j].x = fmaf(W[k], x.x, acc[j].x);
                        acc[j].y = fmaf(W[k], x.y, acc[j].y);
                        acc[j].z = fmaf(W[k], x.z, acc[j].z);
                        acc[j].w = fmaf(W[k], x.w, acc[j].w);
                    }
                }
            }
        }

        // dump acc -> v (each thread overwrites only bytes it staged itself)
#pragma unroll
        for (int j = 0; j < VCHUNK; ++j)
            ((float4*)v[j])[tid] = acc[j];
        __syncthreads();                       // publish v to other threads

        // ---- H phase: horizontal 16-tap, one output column per thread ----
        const int oc = tid;
#pragma unroll
        for (int j = 0; j < VCHUNK; ++j) {
            const float* __restrict__ srow = v[j];
            float r;
            if (oc >= 2 && oc <= 253) {
                const float4* __restrict__ sv = (const float4*)srow + oc;
                const float4 a = sv[-2], b = sv[-1], c = sv[0], d = sv[1], e = sv[2];
                r = W[0] * a.z;                  // tap 0 = v[4oc-6]
                r = fmaf(W[1],  a.w, r);  r = fmaf(W[2],  b.x, r);
                r = fmaf(W[3],  b.y, r);  r = fmaf(W[4],  b.z, r);
                r = fmaf(W[5],  b.w, r);  r = fmaf(W[6],  c.x, r);
                r = fmaf(W[7],  c.y, r);  r = fmaf(W[8],  c.z, r);
                r = fmaf(W[9],  c.w, r);  r = fmaf(W[10], d.x, r);
                r = fmaf(W[11], d.y, r);  r = fmaf(W[12], d.z, r);
                r = fmaf(W[13], d.w, r);  r = fmaf(W[14], e.x, r);
                r = fmaf(W[15], e.y, r);         // tap 15 = v[4oc+9]
            } else {
                r = 0.f;
#pragma unroll
                for (int k = 0; k < NTAP; ++k)
                    r = fmaf(W[k], srow[min(max(4 * oc - 6 + k, 0), IN_W - 1)], r);
            }
            outp[(size_t)j * OUT_W + oc] = r;
        }
        __syncthreads();                       // ring safe for next strip
    }
}

extern "C" void kernel_launch(void* const* d_in, const int* in_sizes, int n_in,
                              void* d_out, int out_size)
{
    const float* in  = (const float*)d_in[0];
    float*       out = (float*)d_out;

    const int nimg = in_sizes[0] / (IN_H * IN_W);       // 24

    dim3 grid(XBLKS, nimg);                             // 16 x 24 = 384 blocks
    bicubic_fused<<<grid, 256>>>(in, out);
}